// round 15
// baseline (speedup 1.0000x reference)
#include <cuda_runtime.h>
#include <math.h>

#define HH 2048
#define WW 2048
#define HWFULL (HH * WW)
#define NE 1024              // E maps (half-res expansions) are 1024x1024

// ---------------- static scratch (no allocations allowed) ----------------
__device__ __align__(16) float g_pyr1[3 * 1024 * 1024];
__device__ __align__(16) float g_pyr2[3 * 512 * 512];
__device__ __align__(16) float g_pyr3[3 * 256 * 256];
__device__ __align__(16) float g_pyr4[3 * 128 * 128];
__device__ __align__(16) float g_pyr5[3 * 64 * 64];
__device__ __align__(16) float g_E2[3 * 1024 * 1024];
__device__ __align__(16) float g_E3[3 * 1024 * 1024];
__device__ __align__(16) float g_E4[3 * 1024 * 1024];
__device__ __align__(16) float g_E5[3 * 1024 * 1024];
// composed up-chain weight tables: [depth-1][coord][tap], + base index
__device__ float g_wtW[4][1024][5];
__device__ int   g_wtB[4][1024];

// ---------------- fused blur (3-tap) + 2x2 mean, float4 / 2-output --------
__global__ void blur_down2_kernel(const float* __restrict__ in, float* __restrict__ out,
                                  int no, float De, float Dm) {
    int x = blockIdx.x * blockDim.x + threadIdx.x;     // output PAIR index
    int y = blockIdx.y * blockDim.y + threadIdx.y;
    int c = blockIdx.z;
    int nh = no >> 1;
    if (x >= nh || y >= no) return;
    int ni = 2 * no;
    int nq = ni >> 2;
    const float4* ip = (const float4*)(in) + (size_t)c * ni * nq;
    float ax = 0.f, ay = 0.f;
#pragma unroll
    for (int j = 0; j < 4; j++) {
        int r = 2 * y - 1 + j;
        if (r < 0 || r >= ni) continue;
        const float4* row = ip + (size_t)r * nq;
        float4 Bc = row[x];
        float a = (x > 0) ? row[x - 1].w : 0.f;
        float d = (x < nh - 1) ? row[x + 1].x : 0.f;
        float wj = (j == 0 || j == 3) ? De : Dm;
        ax += wj * (De * a + Dm * Bc.x + Dm * Bc.y + De * Bc.z);
        ay += wj * (De * Bc.y + Dm * Bc.z + Dm * Bc.w + De * d);
    }
    float2* op = (float2*)(out + (size_t)c * no * no + (size_t)y * no);
    op[x] = make_float2(ax, ay);
}

// ---------------- fused small down chain: pyr2 -> pyr3,pyr4,pyr5 ----------
// Compile-time sizes: divisions become mul-shift, inner loops fully unroll.
template<int SO, int PIN, int NN>
__device__ __forceinline__ void dstage_t(const float* __restrict__ sin,
                                         float* __restrict__ sout,
                                         int offR, int offC,
                                         float De, float Dm, int tid) {
    for (int i = tid; i < SO * SO; i += 256) {
        int v = i / SO, u = i - v * SO;
        int gy = offR + v, gx = offC + u;
        float val = 0.f;
        if (gy >= 0 && gy < NN && gx >= 0 && gx < NN) {
            float acc = 0.f;
#pragma unroll
            for (int j = 0; j < 4; j++) {
                const float* row = sin + (2 * v + j) * PIN + 2 * u;
                float wj = (j == 0 || j == 3) ? De : Dm;
                acc += wj * (De * row[0] + Dm * row[1] + Dm * row[2] + De * row[3]);
            }
            val = acc;
        }
        sout[i] = val;
    }
}

__global__ __launch_bounds__(256)
void down_small_kernel(const float* __restrict__ pyr2,
                       float* __restrict__ pyr3, float* __restrict__ pyr4,
                       float* __restrict__ pyr5, float De, float Dm) {
    __shared__ float s2[46 * 46];
    __shared__ float s3[22 * 22];
    __shared__ float s4[10 * 10];
    int bx = blockIdx.x, by = blockIdx.y, c = blockIdx.z;
    int tid = threadIdx.x;

    const float* p2 = pyr2 + (size_t)c * 512 * 512;
    int r0 = 32 * by - 7, c0 = 32 * bx - 7;
    for (int i = tid; i < 46 * 46; i += 256) {
        int v = i / 46, u = i - v * 46;
        int gr = r0 + v, gc = c0 + u;
        float val = 0.f;
        if (gr >= 0 && gr < 512 && gc >= 0 && gc < 512)
            val = p2[(size_t)gr * 512 + gc];
        s2[i] = val;
    }
    __syncthreads();

    dstage_t<22, 46, 256>(s2, s3, 16 * by - 3, 16 * bx - 3, De, Dm, tid);
    __syncthreads();
    dstage_t<10, 22, 128>(s3, s4, 8 * by - 1, 8 * bx - 1, De, Dm, tid);
    __syncthreads();

    float* p3 = pyr3 + (size_t)c * 256 * 256;
    for (int i = tid; i < 16 * 16; i += 256) {
        int v = i >> 4, u = i & 15;
        p3[(size_t)(16 * by + v) * 256 + 16 * bx + u] = s3[(v + 3) * 22 + u + 3];
    }
    float* p4 = pyr4 + (size_t)c * 128 * 128;
    for (int i = tid; i < 8 * 8; i += 256) {
        int v = i >> 3, u = i & 7;
        p4[(size_t)(8 * by + v) * 128 + 8 * bx + u] = s4[(v + 1) * 10 + u + 1];
    }
    float* p5 = pyr5 + (size_t)c * 64 * 64;
    for (int i = tid; i < 4 * 4; i += 256) {
        int v = i >> 2, u = i & 3;
        float acc = 0.f;
#pragma unroll
        for (int j = 0; j < 4; j++) {
            const float* row = s4 + (2 * v + j) * 10 + 2 * u;
            float wj = (j == 0 || j == 3) ? De : Dm;
            acc += wj * (De * row[0] + Dm * row[1] + Dm * row[2] + De * row[3]);
        }
        p5[(size_t)(4 * by + v) * 64 + 4 * bx + u] = acc;
    }
}

// ---------------- composite (bilinear x2 upsample -> 3-tap blur) weights ---
__device__ __forceinline__ void ub_weights(int o, int n, float w0, float w1,
                                           int& base, float w[3]) {
    base = (o >> 1) - 1;
    w[0] = w[1] = w[2] = 0.f;
    int n2 = n * 2;
#pragma unroll
    for (int d = -1; d <= 1; ++d) {
        int p = o + d;
        if (p < 0 || p >= n2) continue;
        float bw = (d == 0) ? w0 : w1;
        int i = p >> 1;
        if ((p & 1) == 0) {
            w[i - 1 - base] += 0.25f * bw;
            w[i - base]     += 0.75f * bw;
        } else {
            w[i - base]     += 0.75f * bw;
            w[i + 1 - base] += 0.25f * bw;
        }
    }
}

__device__ float up_pixel(const float* __restrict__ E, int n, int ox, int oy,
                          float w0, float w1) {
    int by, bx;
    float wy[3], wx[3];
    ub_weights(oy, n, w0, w1, by, wy);
    ub_weights(ox, n, w0, w1, bx, wx);
    int ry[3], rx[3];
#pragma unroll
    for (int j = 0; j < 3; j++) {
        ry[j] = min(max(by + j, 0), n - 1);
        rx[j] = min(max(bx + j, 0), n - 1);
    }
    float s = 0.f;
#pragma unroll
    for (int jy = 0; jy < 3; jy++) {
        const float* row = E + (size_t)ry[jy] * n;
        s += wy[jy] * (wx[0] * row[rx[0]] + wx[1] * row[rx[1]] + wx[2] * row[rx[2]]);
    }
    return s;
}

// ---------------- exact composed 1-D up-chain weights (support <= 5) -------
__device__ void axis_weights5(int o, int d, int ns, float w0, float w1,
                              int& lo_out, float wv[5]) {
    float v[5];
#pragma unroll
    for (int i = 0; i < 5; i++) v[i] = 0.f;
    v[0] = 1.f;
    int lo = o;
    for (int k = d; k >= 1; --k) {
        int n_in = ns << (k - 1);
        float nv[5];
#pragma unroll
        for (int i = 0; i < 5; i++) nv[i] = 0.f;
        int nlo = (lo >> 1) - 1;
        if (nlo < 0) nlo = 0;
#pragma unroll
        for (int i = 0; i < 5; i++) {
            float w = v[i];
            if (w == 0.f) continue;
            int m = lo + i;
            int b;
            float t[3];
            ub_weights(m, n_in, w0, w1, b, t);
#pragma unroll
            for (int j = 0; j < 3; j++) {
                int cc = min(max(b + j, 0), n_in - 1);
                nv[cc - nlo] += w * t[j];
            }
        }
#pragma unroll
        for (int i = 0; i < 5; i++) v[i] = nv[i];
        lo = nlo;
    }
    lo_out = lo;
#pragma unroll
    for (int i = 0; i < 5; i++) wv[i] = v[i];
}

// ---------------- weight-table precompute (data-independent) ---------------
__global__ void weight_table_kernel(float w0, float w1) {
    int o = blockIdx.x * 64 + threadIdx.x;
    int d = blockIdx.y + 1;
    int ns = 1024 >> d;
    int b;
    float wv[5];
    axis_weights5(o, d, ns, w0, w1, b, wv);
    g_wtB[d - 1][o] = b;
#pragma unroll
    for (int i = 0; i < 5; i++) g_wtW[d - 1][o][i] = wv[i];
}

// ---------------- ONE-launch expansion: pyrL -> E_L directly ---------------
#define SPITCH 38
#define SROWS 38
#define HPITCH 65

__global__ __launch_bounds__(256)
void expand_direct_kernel(const float* __restrict__ pyr2, const float* __restrict__ pyr3,
                          const float* __restrict__ pyr4, const float* __restrict__ pyr5,
                          float* __restrict__ E2, float* __restrict__ E3,
                          float* __restrict__ E4, float* __restrict__ E5) {
    __shared__ float S[SROWS * SPITCH];
    __shared__ float Hs[SROWS * HPITCH];
    __shared__ float swcol[64][5], swrow[64][5];
    __shared__ int sbcol[64], sbrow[64];

    int z = blockIdx.z;
    int c = z >> 2;
    int Lm2 = z & 3;
    int d = Lm2 + 1;
    int ns = 1024 >> d;

    const float* pin = pyr2;
    float* pout = E2;
    if (Lm2 == 1) { pin = pyr3; pout = E3; }
    else if (Lm2 == 2) { pin = pyr4; pout = E4; }
    else if (Lm2 == 3) { pin = pyr5; pout = E5; }
    pin += (size_t)c * ns * ns;
    pout += (size_t)c * NE * NE;

    int X0 = blockIdx.x * 64, Y0 = blockIdx.y * 64;
    int tid = threadIdx.x;

    if (tid < 64) {
        sbcol[tid] = g_wtB[d - 1][X0 + tid];
#pragma unroll
        for (int i = 0; i < 5; i++) swcol[tid][i] = g_wtW[d - 1][X0 + tid][i];
    } else if (tid < 128) {
        int u = tid - 64;
        sbrow[u] = g_wtB[d - 1][Y0 + u];
#pragma unroll
        for (int i = 0; i < 5; i++) swrow[u][i] = g_wtW[d - 1][Y0 + u][i];
    }
    __syncthreads();

    int corig = sbcol[0];
    int rorig = sbrow[0];
    int colSpan = sbcol[63] + 5 - corig;
    int rowSpan = sbrow[63] + 5 - rorig;

    for (int i = tid; i < rowSpan * colSpan; i += 256) {
        int r = i / colSpan, u = i - r * colSpan;
        int gr = min(rorig + r, ns - 1);
        int gc = min(corig + u, ns - 1);
        S[r * SPITCH + u] = pin[(size_t)gr * ns + gc];
    }
    __syncthreads();

    // horizontal pass: thread owns column u; weights hoisted to registers
    {
        int u = tid & 63;
        int bc = sbcol[u] - corig;
        float wc0 = swcol[u][0], wc1 = swcol[u][1], wc2 = swcol[u][2];
        float wc3 = swcol[u][3], wc4 = swcol[u][4];
        for (int r = tid >> 6; r < rowSpan; r += 4) {
            const float* sr = S + r * SPITCH + bc;
            Hs[r * HPITCH + u] = wc0 * sr[0] + wc1 * sr[1] + wc2 * sr[2] +
                                 wc3 * sr[3] + wc4 * sr[4];
        }
    }
    __syncthreads();

    // vertical pass + store: thread owns column u; weights broadcast per v
    {
        int u = tid & 63;
        for (int v = tid >> 6; v < 64; v += 4) {
            const float* hc = Hs + (sbrow[v] - rorig) * HPITCH + u;
            float acc = swrow[v][0] * hc[0] +
                        swrow[v][1] * hc[HPITCH] +
                        swrow[v][2] * hc[2 * HPITCH] +
                        swrow[v][3] * hc[3 * HPITCH] +
                        swrow[v][4] * hc[4 * HPITCH];
            pout[(size_t)(Y0 + v) * NE + (X0 + u)] = acc;
        }
    }
}

// ---------------- blend helpers (R7-verified) -------------------------------
__device__ __forceinline__ const float* level_ptr(int l, const float* E1, const float* E2,
                                                  const float* E3, const float* E4,
                                                  const float* E5) {
    const float* p = E1;
    p = (l == 2) ? E2 : p;
    p = (l == 3) ? E3 : p;
    p = (l == 4) ? E4 : p;
    p = (l == 5) ? E5 : p;
    return p;
}

__device__ __forceinline__ float blend_B(int l, float R) {
    float sprev = exp2f((float)(l - 3));
    float ap = sprev * R * (1.0f / 0.248f);
    float tp = expf(-(ap * ap) * 3.0f);
    float tc = 0.f;
    if (l < 5) {
        float ac = 2.0f * ap;
        tc = expf(-(ac * ac) * 3.0f);
    }
    return (0.5f - tc) / (tp - tc + 1e-5f);
}

__device__ void pixel_slow(int x, int y, int l, float R,
                           const float* __restrict__ img,
                           const float* __restrict__ E1, const float* __restrict__ E2,
                           const float* __restrict__ E3, const float* __restrict__ E4,
                           const float* __restrict__ E5, float* __restrict__ out,
                           float w0, float w1) {
    int pix = y * WW + x;
    if (l == 0) {
        out[pix] = img[pix];
        out[pix + HWFULL] = img[pix + HWFULL];
        out[pix + 2 * HWFULL] = img[pix + 2 * HWFULL];
        return;
    }
    float B = blend_B(l, R);
    const float* Ecur = level_ptr(l, E1, E2, E3, E4, E5);
    const float* Eprev = level_ptr(l - 1, E1, E2, E3, E4, E5);
#pragma unroll
    for (int c = 0; c < 3; c++) {
        float vc = up_pixel(Ecur + c * NE * NE, NE, x, y, w0, w1);
        float vp = (l == 1) ? img[pix + c * HWFULL]
                            : up_pixel(Eprev + c * NE * NE, NE, x, y, w0, w1);
        out[pix + c * HWFULL] = B * vp + (1.f - B) * vc;
    }
}

__device__ void quad_global(int qx, int qy, int l0, const float B[2][2],
                            const float* __restrict__ img,
                            const float* __restrict__ cur, const float* __restrict__ prv,
                            float* __restrict__ out,
                            float we0, float we1, float we2) {
    int pix0 = (2 * qy) * WW + 2 * qx;
    int wbase = (qy - 1) * NE + (qx - 1);
#pragma unroll
    for (int c = 0; c < 3; c++) {
        const float* pc = cur + c * NE * NE + wbase;
        float he[3], ho[3];
#pragma unroll
        for (int j = 0; j < 3; j++) {
            float a = pc[j * NE], b = pc[j * NE + 1], d = pc[j * NE + 2];
            he[j] = we0 * a + we1 * b + we2 * d;
            ho[j] = we2 * a + we1 * b + we0 * d;
        }
        float vc[2][2];
        vc[0][0] = we0 * he[0] + we1 * he[1] + we2 * he[2];
        vc[0][1] = we0 * ho[0] + we1 * ho[1] + we2 * ho[2];
        vc[1][0] = we2 * he[0] + we1 * he[1] + we0 * he[2];
        vc[1][1] = we2 * ho[0] + we1 * ho[1] + we0 * ho[2];

        float vp[2][2];
        if (l0 == 1) {
            float2 i0 = *(const float2*)(img + pix0 + c * HWFULL);
            float2 i1 = *(const float2*)(img + pix0 + WW + c * HWFULL);
            vp[0][0] = i0.x; vp[0][1] = i0.y; vp[1][0] = i1.x; vp[1][1] = i1.y;
        } else {
            const float* pp = prv + c * NE * NE + wbase;
            float pe[3], po[3];
#pragma unroll
            for (int j = 0; j < 3; j++) {
                float a = pp[j * NE], b = pp[j * NE + 1], d = pp[j * NE + 2];
                pe[j] = we0 * a + we1 * b + we2 * d;
                po[j] = we2 * a + we1 * b + we0 * d;
            }
            vp[0][0] = we0 * pe[0] + we1 * pe[1] + we2 * pe[2];
            vp[0][1] = we0 * po[0] + we1 * po[1] + we2 * po[2];
            vp[1][0] = we2 * pe[0] + we1 * pe[1] + we0 * pe[2];
            vp[1][1] = we2 * po[0] + we1 * po[1] + we0 * po[2];
        }
        float2 o0, o1;
        o0.x = B[0][0] * vp[0][0] + (1.f - B[0][0]) * vc[0][0];
        o0.y = B[0][1] * vp[0][1] + (1.f - B[0][1]) * vc[0][1];
        o1.x = B[1][0] * vp[1][0] + (1.f - B[1][0]) * vc[1][0];
        o1.y = B[1][1] * vp[1][1] + (1.f - B[1][1]) * vc[1][1];
        *(float2*)(out + pix0 + c * HWFULL) = o0;
        *(float2*)(out + pix0 + WW + c * HWFULL) = o1;
    }
}

// ---------------- blend: smem fast path covering 1- and 2-level blocks -----
#define TQX 32
#define TQY 8
#define TPITCH 34
#define TROWS 10

__device__ __forceinline__ float evalw(const float w[TROWS][TPITCH], int ty, int tx,
                                       int oxo, int oyo,
                                       float we0, float we1, float we2) {
    float h[3];
#pragma unroll
    for (int j = 0; j < 3; j++) {
        float a = w[ty + j][tx], b = w[ty + j][tx + 1], d = w[ty + j][tx + 2];
        h[j] = oxo ? (we2 * a + we1 * b + we0 * d) : (we0 * a + we1 * b + we2 * d);
    }
    return oyo ? (we2 * h[0] + we1 * h[1] + we0 * h[2])
               : (we0 * h[0] + we1 * h[1] + we2 * h[2]);
}

__global__ __launch_bounds__(256, 4)
void blend_quad_kernel(const float* __restrict__ img, const float* __restrict__ fixs,
                       const float* __restrict__ E1, const float* __restrict__ E2,
                       const float* __restrict__ E3, const float* __restrict__ E4,
                       const float* __restrict__ E5, float* __restrict__ out,
                       float w0, float w1, float we0, float we1, float we2,
                       float om0, float om1, float om2, float om3, float om4) {
    __shared__ float s_w[3][3][TROWS][TPITCH];
    __shared__ int s_mask;

    int tx = threadIdx.x, ty = threadIdx.y;
    int qx = blockIdx.x * TQX + tx;
    int qy = blockIdx.y * TQY + ty;
    int tid = ty * TQX + tx;

    float d2q[2][2] = {{3.4e38f, 3.4e38f}, {3.4e38f, 3.4e38f}};
    float x0 = (float)(2 * qx), y0 = (float)(2 * qy);
#pragma unroll
    for (int k = 0; k < 4; k++) {
        float dx = x0 - fixs[2 * k];
        float dy = y0 - fixs[2 * k + 1];
        float d00 = dx * dx + dy * dy;
        float tX = 2.f * dx + 1.f;
        float tY = 2.f * dy + 1.f;
        float d01 = d00 + tX;
        d2q[0][0] = fminf(d2q[0][0], d00);
        d2q[0][1] = fminf(d2q[0][1], d01);
        d2q[1][0] = fminf(d2q[1][0], d00 + tY);
        d2q[1][1] = fminf(d2q[1][1], d01 + tY);
    }

    int lv[2][2];
    float Rv[2][2];
#pragma unroll
    for (int py = 0; py < 2; py++)
#pragma unroll
        for (int px = 0; px < 2; px++) {
            float theta = sqrtf(d2q[py][px]) * (1.0f / 7.5f);
            float R = 2.5f / (theta + 2.5f);
            Rv[py][px] = R;
            lv[py][px] = (R <= om0) + (R <= om1) + (R <= om2) +
                         (R <= om3) + (R <= om4);
        }

    if (tid == 0) s_mask = 0;
    __syncthreads();
    int myMask = (1 << lv[0][0]) | (1 << lv[0][1]) | (1 << lv[1][0]) | (1 << lv[1][1]);
    atomicOr(&s_mask, myMask);
    __syncthreads();
    int mask = s_mask;
    int lmin = __ffs(mask) - 1;
    int lmax = 31 - __clz(mask);
    bool block_border = (blockIdx.x == 0) || (blockIdx.x == gridDim.x - 1) ||
                        (blockIdx.y == 0) || (blockIdx.y == gridDim.y - 1);

    int pix0 = (2 * qy) * WW + 2 * qx;

    if (!block_border && (lmax - lmin) <= 1) {
        if (mask == 1) {
#pragma unroll
            for (int c = 0; c < 3; c++) {
                *(float2*)(out + pix0 + c * HWFULL) =
                    *(const float2*)(img + pix0 + c * HWFULL);
                *(float2*)(out + pix0 + WW + c * HWFULL) =
                    *(const float2*)(img + pix0 + WW + c * HWFULL);
            }
            return;
        }
        int base = max(lmin, 1);
        bool hasP = (base >= 2);
        bool hasN = (lmax > base);
        const float* Ebase = level_ptr(base, E1, E2, E3, E4, E5);
        const float* Eprv = hasP ? level_ptr(base - 1, E1, E2, E3, E4, E5) : Ebase;
        const float* Enxt = hasN ? level_ptr(base + 1, E1, E2, E3, E4, E5) : Ebase;

        int ox0 = blockIdx.x * TQX - 1;
        int oy0 = blockIdx.y * TQY - 1;
        const int NFILL = 3 * TROWS * TPITCH;
        for (int i = tid; i < NFILL; i += 256) {
            int c = i / (TROWS * TPITCH);
            int rem = i - c * (TROWS * TPITCH);
            int r = rem / TPITCH, col = rem - r * TPITCH;
            size_t g = (size_t)c * NE * NE + (size_t)(oy0 + r) * NE + (ox0 + col);
            s_w[1][c][r][col] = Ebase[g];
            if (hasP) s_w[0][c][r][col] = Eprv[g];
            if (hasN) s_w[2][c][r][col] = Enxt[g];
        }
        __syncthreads();

        int lq = lv[0][0];
        bool uniq = (lv[0][1] == lq) && (lv[1][0] == lq) && (lv[1][1] == lq);

        if (uniq && lq == 0) {
#pragma unroll
            for (int c = 0; c < 3; c++) {
                *(float2*)(out + pix0 + c * HWFULL) =
                    *(const float2*)(img + pix0 + c * HWFULL);
                *(float2*)(out + pix0 + WW + c * HWFULL) =
                    *(const float2*)(img + pix0 + WW + c * HWFULL);
            }
            return;
        }

        if (uniq) {
            int cs = 1 + (lq - base);
            float B[2][2];
#pragma unroll
            for (int py = 0; py < 2; py++)
#pragma unroll
                for (int px = 0; px < 2; px++)
                    B[py][px] = blend_B(lq, Rv[py][px]);

#pragma unroll
            for (int c = 0; c < 3; c++) {
                const float (*wc)[TPITCH] = s_w[cs][c];
                float he[3], ho[3];
#pragma unroll
                for (int j = 0; j < 3; j++) {
                    float a = wc[ty + j][tx], b = wc[ty + j][tx + 1],
                          d = wc[ty + j][tx + 2];
                    he[j] = we0 * a + we1 * b + we2 * d;
                    ho[j] = we2 * a + we1 * b + we0 * d;
                }
                float vc[2][2];
                vc[0][0] = we0 * he[0] + we1 * he[1] + we2 * he[2];
                vc[0][1] = we0 * ho[0] + we1 * ho[1] + we2 * ho[2];
                vc[1][0] = we2 * he[0] + we1 * he[1] + we0 * he[2];
                vc[1][1] = we2 * ho[0] + we1 * ho[1] + we0 * ho[2];

                float vp[2][2];
                if (lq == 1) {
                    float2 i0 = *(const float2*)(img + pix0 + c * HWFULL);
                    float2 i1 = *(const float2*)(img + pix0 + WW + c * HWFULL);
                    vp[0][0] = i0.x; vp[0][1] = i0.y; vp[1][0] = i1.x; vp[1][1] = i1.y;
                } else {
                    const float (*wp)[TPITCH] = s_w[cs - 1][c];
                    float pe[3], po[3];
#pragma unroll
                    for (int j = 0; j < 3; j++) {
                        float a = wp[ty + j][tx], b = wp[ty + j][tx + 1],
                              d = wp[ty + j][tx + 2];
                        pe[j] = we0 * a + we1 * b + we2 * d;
                        po[j] = we2 * a + we1 * b + we0 * d;
                    }
                    vp[0][0] = we0 * pe[0] + we1 * pe[1] + we2 * pe[2];
                    vp[0][1] = we0 * po[0] + we1 * po[1] + we2 * po[2];
                    vp[1][0] = we2 * pe[0] + we1 * pe[1] + we0 * pe[2];
                    vp[1][1] = we2 * po[0] + we1 * po[1] + we0 * po[2];
                }
                float2 o0, o1;
                o0.x = B[0][0] * vp[0][0] + (1.f - B[0][0]) * vc[0][0];
                o0.y = B[0][1] * vp[0][1] + (1.f - B[0][1]) * vc[0][1];
                o1.x = B[1][0] * vp[1][0] + (1.f - B[1][0]) * vc[1][0];
                o1.y = B[1][1] * vp[1][1] + (1.f - B[1][1]) * vc[1][1];
                *(float2*)(out + pix0 + c * HWFULL) = o0;
                *(float2*)(out + pix0 + WW + c * HWFULL) = o1;
            }
            return;
        }

        float px_out[2][2][3];
#pragma unroll
        for (int py = 0; py < 2; py++)
#pragma unroll
            for (int px = 0; px < 2; px++) {
                int l = lv[py][px];
                int pp = pix0 + py * WW + px;
                if (l == 0) {
#pragma unroll
                    for (int c = 0; c < 3; c++)
                        px_out[py][px][c] = img[pp + c * HWFULL];
                } else {
                    int cs = 1 + (l - base);
                    float B = blend_B(l, Rv[py][px]);
#pragma unroll
                    for (int c = 0; c < 3; c++) {
                        float vc = evalw(s_w[cs][c], ty, tx, px, py, we0, we1, we2);
                        float vp = (l == 1) ? img[pp + c * HWFULL]
                                 : evalw(s_w[cs - 1][c], ty, tx, px, py, we0, we1, we2);
                        px_out[py][px][c] = B * vp + (1.f - B) * vc;
                    }
                }
            }
#pragma unroll
        for (int c = 0; c < 3; c++) {
            float2 o0, o1;
            o0.x = px_out[0][0][c]; o0.y = px_out[0][1][c];
            o1.x = px_out[1][0][c]; o1.y = px_out[1][1][c];
            *(float2*)(out + pix0 + c * HWFULL) = o0;
            *(float2*)(out + pix0 + WW + c * HWFULL) = o1;
        }
        return;
    }

    // fallback: border blocks / >2-level blocks (rare)
    int l0 = lv[0][0];
    bool uni = (lv[0][1] == l0) && (lv[1][0] == l0) && (lv[1][1] == l0);
    bool qborder = (qx == 0) | (qx >= NE - 1) | (qy == 0) | (qy >= NE - 1);

    if (uni && l0 == 0) {
#pragma unroll
        for (int c = 0; c < 3; c++) {
            *(float2*)(out + pix0 + c * HWFULL) =
                *(const float2*)(img + pix0 + c * HWFULL);
            *(float2*)(out + pix0 + WW + c * HWFULL) =
                *(const float2*)(img + pix0 + WW + c * HWFULL);
        }
        return;
    }
    if (!uni || qborder) {
#pragma unroll
        for (int py = 0; py < 2; py++)
#pragma unroll
            for (int px = 0; px < 2; px++)
                pixel_slow(2 * qx + px, 2 * qy + py, lv[py][px], Rv[py][px],
                           img, E1, E2, E3, E4, E5, out, w0, w1);
        return;
    }
    float B[2][2];
#pragma unroll
    for (int py = 0; py < 2; py++)
#pragma unroll
        for (int px = 0; px < 2; px++)
            B[py][px] = blend_B(l0, Rv[py][px]);
    const float* cur = level_ptr(l0, E1, E2, E3, E4, E5);
    const float* prv = level_ptr(l0 - 1, E1, E2, E3, E4, E5);
    quad_global(qx, qy, l0, B, img, cur, prv, out, we0, we1, we2);
}

// ---------------- host launch ---------------------------------------------
extern "C" void kernel_launch(void* const* d_in, const int* in_sizes, int n_in,
                              void* d_out, int out_size) {
    const float* img = (const float*)d_in[0];
    const float* fixs = (const float*)d_in[1];
    float* out = (float*)d_out;

    float *pyr1, *pyr2, *pyr3, *pyr4, *pyr5, *E2, *E3, *E4, *E5;
    cudaGetSymbolAddress((void**)&pyr1, g_pyr1);
    cudaGetSymbolAddress((void**)&pyr2, g_pyr2);
    cudaGetSymbolAddress((void**)&pyr3, g_pyr3);
    cudaGetSymbolAddress((void**)&pyr4, g_pyr4);
    cudaGetSymbolAddress((void**)&pyr5, g_pyr5);
    cudaGetSymbolAddress((void**)&E2, g_E2);
    cudaGetSymbolAddress((void**)&E3, g_E3);
    cudaGetSymbolAddress((void**)&E4, g_E4);
    cudaGetSymbolAddress((void**)&E5, g_E5);

    // Gaussian taps (w2 ~ 7.5e-15 dropped from taps; kept in normalization)
    double s2 = 2.0 * 0.248 * 0.248;
    double g1 = exp(-1.0 / s2);
    double g2 = exp(-4.0 / s2);
    double nrm = 1.0 + 2.0 * g1 + 2.0 * g2;
    float w0 = (float)(1.0 / nrm);
    float w1 = (float)(g1 / nrm);
    float De = (float)(0.5 * g1 / nrm);
    float Dm = (float)(0.5 * (1.0 + g1) / nrm);
    float we0 = 0.25f * w0 + 0.75f * w1;
    float we1 = 0.75f * w0 + w1;
    float we2 = 0.25f * w1;

    double ob = sqrt(log(2.0) / 3.0) * 0.248;
    float om0 = (float)(ob * 4.0);
    float om1 = (float)(ob * 2.0);
    float om2 = (float)(ob);
    float om3 = (float)(ob * 0.5);
    float om4 = (float)(ob * 0.25);

    dim3 blk(32, 8);

    // Composed-weight tables (data-independent, tiny)
    weight_table_kernel<<<dim3(16, 4), 64>>>(w0, w1);

    // Gaussian pyramid: float4 2-output big levels + templated small chain
    blur_down2_kernel<<<dim3(16, 128, 3), blk>>>(img, pyr1, 1024, De, Dm);
    blur_down2_kernel<<<dim3(8, 64, 3),   blk>>>(pyr1, pyr2, 512, De, Dm);
    down_small_kernel<<<dim3(16, 16, 3), 256>>>(pyr2, pyr3, pyr4, pyr5, De, Dm);

    // ALL expansions (E2..E5) in ONE launch via table-driven composed weights
    expand_direct_kernel<<<dim3(16, 16, 12), 256>>>(pyr2, pyr3, pyr4, pyr5,
                                                    E2, E3, E4, E5);

    // Final blend (R7-verified)
    blend_quad_kernel<<<dim3(NE / 32, NE / 8), blk>>>(img, fixs, pyr1, E2, E3, E4, E5,
                                                      out, w0, w1, we0, we1, we2,
                                                      om0, om1, om2, om3, om4);
}

// round 16
// speedup vs baseline: 1.0404x; 1.0404x over previous
#include <cuda_runtime.h>
#include <math.h>

#define HH 2048
#define WW 2048
#define HWFULL (HH * WW)
#define NE 1024              // E maps (half-res expansions) are 1024x1024

// ---------------- static scratch (no allocations allowed) ----------------
__device__ __align__(16) float g_pyr1[3 * 1024 * 1024];
__device__ __align__(16) float g_pyr2[3 * 512 * 512];
__device__ __align__(16) float g_pyr3[3 * 256 * 256];
__device__ __align__(16) float g_pyr4[3 * 128 * 128];
__device__ __align__(16) float g_pyr5[3 * 64 * 64];
__device__ __align__(16) float g_E2[3 * 1024 * 1024];
__device__ __align__(16) float g_E3[3 * 1024 * 1024];
__device__ __align__(16) float g_E4[3 * 1024 * 1024];
__device__ __align__(16) float g_E5[3 * 1024 * 1024];
// composed up-chain weight tables: [depth-1][coord][tap], + base index
__device__ float g_wtW[4][1024][5];
__device__ int   g_wtB[4][1024];

// ---------------- fused blur (3-tap) + 2x2 mean, float4 / 2-output --------
__global__ void blur_down2_kernel(const float* __restrict__ in, float* __restrict__ out,
                                  int no, float De, float Dm) {
    int x = blockIdx.x * blockDim.x + threadIdx.x;     // output PAIR index
    int y = blockIdx.y * blockDim.y + threadIdx.y;
    int c = blockIdx.z;
    int nh = no >> 1;
    if (x >= nh || y >= no) return;
    int ni = 2 * no;
    int nq = ni >> 2;
    const float4* ip = (const float4*)(in) + (size_t)c * ni * nq;
    float ax = 0.f, ay = 0.f;
#pragma unroll
    for (int j = 0; j < 4; j++) {
        int r = 2 * y - 1 + j;
        if (r < 0 || r >= ni) continue;
        const float4* row = ip + (size_t)r * nq;
        float4 Bc = row[x];
        float a = (x > 0) ? row[x - 1].w : 0.f;
        float d = (x < nh - 1) ? row[x + 1].x : 0.f;
        float wj = (j == 0 || j == 3) ? De : Dm;
        ax += wj * (De * a + Dm * Bc.x + Dm * Bc.y + De * Bc.z);
        ay += wj * (De * Bc.y + Dm * Bc.z + Dm * Bc.w + De * d);
    }
    float2* op = (float2*)(out + (size_t)c * no * no + (size_t)y * no);
    op[x] = make_float2(ax, ay);
}

// ---------------- fused small down chain: pyr2 -> pyr3,pyr4,pyr5 ----------
template<int SO, int PIN, int NN>
__device__ __forceinline__ void dstage_t(const float* __restrict__ sin,
                                         float* __restrict__ sout,
                                         int offR, int offC,
                                         float De, float Dm, int tid) {
    for (int i = tid; i < SO * SO; i += 256) {
        int v = i / SO, u = i - v * SO;
        int gy = offR + v, gx = offC + u;
        float val = 0.f;
        if (gy >= 0 && gy < NN && gx >= 0 && gx < NN) {
            float acc = 0.f;
#pragma unroll
            for (int j = 0; j < 4; j++) {
                const float* row = sin + (2 * v + j) * PIN + 2 * u;
                float wj = (j == 0 || j == 3) ? De : Dm;
                acc += wj * (De * row[0] + Dm * row[1] + Dm * row[2] + De * row[3]);
            }
            val = acc;
        }
        sout[i] = val;
    }
}

__global__ __launch_bounds__(256)
void down_small_kernel(const float* __restrict__ pyr2,
                       float* __restrict__ pyr3, float* __restrict__ pyr4,
                       float* __restrict__ pyr5, float De, float Dm) {
    __shared__ float s2[46 * 46];
    __shared__ float s3[22 * 22];
    __shared__ float s4[10 * 10];
    int bx = blockIdx.x, by = blockIdx.y, c = blockIdx.z;
    int tid = threadIdx.x;

    const float* p2 = pyr2 + (size_t)c * 512 * 512;
    int r0 = 32 * by - 7, c0 = 32 * bx - 7;
    for (int i = tid; i < 46 * 46; i += 256) {
        int v = i / 46, u = i - v * 46;
        int gr = r0 + v, gc = c0 + u;
        float val = 0.f;
        if (gr >= 0 && gr < 512 && gc >= 0 && gc < 512)
            val = p2[(size_t)gr * 512 + gc];
        s2[i] = val;
    }
    __syncthreads();

    dstage_t<22, 46, 256>(s2, s3, 16 * by - 3, 16 * bx - 3, De, Dm, tid);
    __syncthreads();
    dstage_t<10, 22, 128>(s3, s4, 8 * by - 1, 8 * bx - 1, De, Dm, tid);
    __syncthreads();

    float* p3 = pyr3 + (size_t)c * 256 * 256;
    for (int i = tid; i < 16 * 16; i += 256) {
        int v = i >> 4, u = i & 15;
        p3[(size_t)(16 * by + v) * 256 + 16 * bx + u] = s3[(v + 3) * 22 + u + 3];
    }
    float* p4 = pyr4 + (size_t)c * 128 * 128;
    for (int i = tid; i < 8 * 8; i += 256) {
        int v = i >> 3, u = i & 7;
        p4[(size_t)(8 * by + v) * 128 + 8 * bx + u] = s4[(v + 1) * 10 + u + 1];
    }
    float* p5 = pyr5 + (size_t)c * 64 * 64;
    for (int i = tid; i < 4 * 4; i += 256) {
        int v = i >> 2, u = i & 3;
        float acc = 0.f;
#pragma unroll
        for (int j = 0; j < 4; j++) {
            const float* row = s4 + (2 * v + j) * 10 + 2 * u;
            float wj = (j == 0 || j == 3) ? De : Dm;
            acc += wj * (De * row[0] + Dm * row[1] + Dm * row[2] + De * row[3]);
        }
        p5[(size_t)(4 * by + v) * 64 + 4 * bx + u] = acc;
    }
}

// ---------------- composite (bilinear x2 upsample -> 3-tap blur) weights ---
__device__ __forceinline__ void ub_weights(int o, int n, float w0, float w1,
                                           int& base, float w[3]) {
    base = (o >> 1) - 1;
    w[0] = w[1] = w[2] = 0.f;
    int n2 = n * 2;
#pragma unroll
    for (int d = -1; d <= 1; ++d) {
        int p = o + d;
        if (p < 0 || p >= n2) continue;
        float bw = (d == 0) ? w0 : w1;
        int i = p >> 1;
        if ((p & 1) == 0) {
            w[i - 1 - base] += 0.25f * bw;
            w[i - base]     += 0.75f * bw;
        } else {
            w[i - base]     += 0.75f * bw;
            w[i + 1 - base] += 0.25f * bw;
        }
    }
}

__device__ float up_pixel(const float* __restrict__ E, int n, int ox, int oy,
                          float w0, float w1) {
    int by, bx;
    float wy[3], wx[3];
    ub_weights(oy, n, w0, w1, by, wy);
    ub_weights(ox, n, w0, w1, bx, wx);
    int ry[3], rx[3];
#pragma unroll
    for (int j = 0; j < 3; j++) {
        ry[j] = min(max(by + j, 0), n - 1);
        rx[j] = min(max(bx + j, 0), n - 1);
    }
    float s = 0.f;
#pragma unroll
    for (int jy = 0; jy < 3; jy++) {
        const float* row = E + (size_t)ry[jy] * n;
        s += wy[jy] * (wx[0] * row[rx[0]] + wx[1] * row[rx[1]] + wx[2] * row[rx[2]]);
    }
    return s;
}

// ---------------- exact composed 1-D up-chain weights (support <= 5) -------
__device__ void axis_weights5(int o, int d, int ns, float w0, float w1,
                              int& lo_out, float wv[5]) {
    float v[5];
#pragma unroll
    for (int i = 0; i < 5; i++) v[i] = 0.f;
    v[0] = 1.f;
    int lo = o;
    for (int k = d; k >= 1; --k) {
        int n_in = ns << (k - 1);
        float nv[5];
#pragma unroll
        for (int i = 0; i < 5; i++) nv[i] = 0.f;
        int nlo = (lo >> 1) - 1;
        if (nlo < 0) nlo = 0;
#pragma unroll
        for (int i = 0; i < 5; i++) {
            float w = v[i];
            if (w == 0.f) continue;
            int m = lo + i;
            int b;
            float t[3];
            ub_weights(m, n_in, w0, w1, b, t);
#pragma unroll
            for (int j = 0; j < 3; j++) {
                int cc = min(max(b + j, 0), n_in - 1);
                nv[cc - nlo] += w * t[j];
            }
        }
#pragma unroll
        for (int i = 0; i < 5; i++) v[i] = nv[i];
        lo = nlo;
    }
    lo_out = lo;
#pragma unroll
    for (int i = 0; i < 5; i++) wv[i] = v[i];
}

// ---------------- weight-table precompute (data-independent) ---------------
__global__ void weight_table_kernel(float w0, float w1) {
    int o = blockIdx.x * 64 + threadIdx.x;
    int d = blockIdx.y + 1;
    int ns = 1024 >> d;
    int b;
    float wv[5];
    axis_weights5(o, d, ns, w0, w1, b, wv);
    g_wtB[d - 1][o] = b;
#pragma unroll
    for (int i = 0; i < 5; i++) g_wtW[d - 1][o][i] = wv[i];
}

// ---------------- expansion: pyrL -> E_L directly (depth-range select) -----
#define SPITCH 38
#define SROWS 38
#define HPITCH 65

__global__ __launch_bounds__(256)
void expand_direct_kernel(const float* __restrict__ pyr2, const float* __restrict__ pyr3,
                          const float* __restrict__ pyr4, const float* __restrict__ pyr5,
                          float* __restrict__ E2, float* __restrict__ E3,
                          float* __restrict__ E4, float* __restrict__ E5,
                          int Lm2base, int nd) {
    __shared__ float S[SROWS * SPITCH];
    __shared__ float Hs[SROWS * HPITCH];
    __shared__ float swcol[64][5], swrow[64][5];
    __shared__ int sbcol[64], sbrow[64];

    int z = blockIdx.z;
    int c, Lm2;
    if (nd == 1) { c = z; Lm2 = Lm2base; }
    else { c = z / 3; Lm2 = Lm2base + (z - c * 3); }
    int d = Lm2 + 1;
    int ns = 1024 >> d;

    const float* pin = pyr2;
    float* pout = E2;
    if (Lm2 == 1) { pin = pyr3; pout = E3; }
    else if (Lm2 == 2) { pin = pyr4; pout = E4; }
    else if (Lm2 == 3) { pin = pyr5; pout = E5; }
    pin += (size_t)c * ns * ns;
    pout += (size_t)c * NE * NE;

    int X0 = blockIdx.x * 64, Y0 = blockIdx.y * 64;
    int tid = threadIdx.x;

    if (tid < 64) {
        sbcol[tid] = g_wtB[d - 1][X0 + tid];
#pragma unroll
        for (int i = 0; i < 5; i++) swcol[tid][i] = g_wtW[d - 1][X0 + tid][i];
    } else if (tid < 128) {
        int u = tid - 64;
        sbrow[u] = g_wtB[d - 1][Y0 + u];
#pragma unroll
        for (int i = 0; i < 5; i++) swrow[u][i] = g_wtW[d - 1][Y0 + u][i];
    }
    __syncthreads();

    int corig = sbcol[0];
    int rorig = sbrow[0];
    int colSpan = sbcol[63] + 5 - corig;
    int rowSpan = sbrow[63] + 5 - rorig;

    for (int i = tid; i < rowSpan * colSpan; i += 256) {
        int r = i / colSpan, u = i - r * colSpan;
        int gr = min(rorig + r, ns - 1);
        int gc = min(corig + u, ns - 1);
        S[r * SPITCH + u] = pin[(size_t)gr * ns + gc];
    }
    __syncthreads();

    // horizontal pass: thread owns column u; weights hoisted to registers
    {
        int u = tid & 63;
        int bc = sbcol[u] - corig;
        float wc0 = swcol[u][0], wc1 = swcol[u][1], wc2 = swcol[u][2];
        float wc3 = swcol[u][3], wc4 = swcol[u][4];
        for (int r = tid >> 6; r < rowSpan; r += 4) {
            const float* sr = S + r * SPITCH + bc;
            Hs[r * HPITCH + u] = wc0 * sr[0] + wc1 * sr[1] + wc2 * sr[2] +
                                 wc3 * sr[3] + wc4 * sr[4];
        }
    }
    __syncthreads();

    // vertical pass + store
    {
        int u = tid & 63;
        for (int v = tid >> 6; v < 64; v += 4) {
            const float* hc = Hs + (sbrow[v] - rorig) * HPITCH + u;
            float acc = swrow[v][0] * hc[0] +
                        swrow[v][1] * hc[HPITCH] +
                        swrow[v][2] * hc[2 * HPITCH] +
                        swrow[v][3] * hc[3 * HPITCH] +
                        swrow[v][4] * hc[4 * HPITCH];
            pout[(size_t)(Y0 + v) * NE + (X0 + u)] = acc;
        }
    }
}

// ---------------- blend helpers (R7-verified) -------------------------------
__device__ __forceinline__ const float* level_ptr(int l, const float* E1, const float* E2,
                                                  const float* E3, const float* E4,
                                                  const float* E5) {
    const float* p = E1;
    p = (l == 2) ? E2 : p;
    p = (l == 3) ? E3 : p;
    p = (l == 4) ? E4 : p;
    p = (l == 5) ? E5 : p;
    return p;
}

__device__ __forceinline__ float blend_B(int l, float R) {
    float sprev = exp2f((float)(l - 3));
    float ap = sprev * R * (1.0f / 0.248f);
    float tp = expf(-(ap * ap) * 3.0f);
    float tc = 0.f;
    if (l < 5) {
        float ac = 2.0f * ap;
        tc = expf(-(ac * ac) * 3.0f);
    }
    return (0.5f - tc) / (tp - tc + 1e-5f);
}

__device__ void pixel_slow(int x, int y, int l, float R,
                           const float* __restrict__ img,
                           const float* __restrict__ E1, const float* __restrict__ E2,
                           const float* __restrict__ E3, const float* __restrict__ E4,
                           const float* __restrict__ E5, float* __restrict__ out,
                           float w0, float w1) {
    int pix = y * WW + x;
    if (l == 0) {
        out[pix] = img[pix];
        out[pix + HWFULL] = img[pix + HWFULL];
        out[pix + 2 * HWFULL] = img[pix + 2 * HWFULL];
        return;
    }
    float B = blend_B(l, R);
    const float* Ecur = level_ptr(l, E1, E2, E3, E4, E5);
    const float* Eprev = level_ptr(l - 1, E1, E2, E3, E4, E5);
#pragma unroll
    for (int c = 0; c < 3; c++) {
        float vc = up_pixel(Ecur + c * NE * NE, NE, x, y, w0, w1);
        float vp = (l == 1) ? img[pix + c * HWFULL]
                            : up_pixel(Eprev + c * NE * NE, NE, x, y, w0, w1);
        out[pix + c * HWFULL] = B * vp + (1.f - B) * vc;
    }
}

__device__ void quad_global(int qx, int qy, int l0, const float B[2][2],
                            const float* __restrict__ img,
                            const float* __restrict__ cur, const float* __restrict__ prv,
                            float* __restrict__ out,
                            float we0, float we1, float we2) {
    int pix0 = (2 * qy) * WW + 2 * qx;
    int wbase = (qy - 1) * NE + (qx - 1);
#pragma unroll
    for (int c = 0; c < 3; c++) {
        const float* pc = cur + c * NE * NE + wbase;
        float he[3], ho[3];
#pragma unroll
        for (int j = 0; j < 3; j++) {
            float a = pc[j * NE], b = pc[j * NE + 1], d = pc[j * NE + 2];
            he[j] = we0 * a + we1 * b + we2 * d;
            ho[j] = we2 * a + we1 * b + we0 * d;
        }
        float vc[2][2];
        vc[0][0] = we0 * he[0] + we1 * he[1] + we2 * he[2];
        vc[0][1] = we0 * ho[0] + we1 * ho[1] + we2 * ho[2];
        vc[1][0] = we2 * he[0] + we1 * he[1] + we0 * he[2];
        vc[1][1] = we2 * ho[0] + we1 * ho[1] + we0 * ho[2];

        float vp[2][2];
        if (l0 == 1) {
            float2 i0 = *(const float2*)(img + pix0 + c * HWFULL);
            float2 i1 = *(const float2*)(img + pix0 + WW + c * HWFULL);
            vp[0][0] = i0.x; vp[0][1] = i0.y; vp[1][0] = i1.x; vp[1][1] = i1.y;
        } else {
            const float* pp = prv + c * NE * NE + wbase;
            float pe[3], po[3];
#pragma unroll
            for (int j = 0; j < 3; j++) {
                float a = pp[j * NE], b = pp[j * NE + 1], d = pp[j * NE + 2];
                pe[j] = we0 * a + we1 * b + we2 * d;
                po[j] = we2 * a + we1 * b + we0 * d;
            }
            vp[0][0] = we0 * pe[0] + we1 * pe[1] + we2 * pe[2];
            vp[0][1] = we0 * po[0] + we1 * po[1] + we2 * po[2];
            vp[1][0] = we2 * pe[0] + we1 * pe[1] + we0 * pe[2];
            vp[1][1] = we2 * po[0] + we1 * po[1] + we0 * po[2];
        }
        float2 o0, o1;
        o0.x = B[0][0] * vp[0][0] + (1.f - B[0][0]) * vc[0][0];
        o0.y = B[0][1] * vp[0][1] + (1.f - B[0][1]) * vc[0][1];
        o1.x = B[1][0] * vp[1][0] + (1.f - B[1][0]) * vc[1][0];
        o1.y = B[1][1] * vp[1][1] + (1.f - B[1][1]) * vc[1][1];
        *(float2*)(out + pix0 + c * HWFULL) = o0;
        *(float2*)(out + pix0 + WW + c * HWFULL) = o1;
    }
}

// ---------------- blend: smem fast path covering 1- and 2-level blocks -----
#define TQX 32
#define TQY 8
#define TPITCH 34
#define TROWS 10

__device__ __forceinline__ float evalw(const float w[TROWS][TPITCH], int ty, int tx,
                                       int oxo, int oyo,
                                       float we0, float we1, float we2) {
    float h[3];
#pragma unroll
    for (int j = 0; j < 3; j++) {
        float a = w[ty + j][tx], b = w[ty + j][tx + 1], d = w[ty + j][tx + 2];
        h[j] = oxo ? (we2 * a + we1 * b + we0 * d) : (we0 * a + we1 * b + we2 * d);
    }
    return oyo ? (we2 * h[0] + we1 * h[1] + we0 * h[2])
               : (we0 * h[0] + we1 * h[1] + we2 * h[2]);
}

__global__ __launch_bounds__(256, 4)
void blend_quad_kernel(const float* __restrict__ img, const float* __restrict__ fixs,
                       const float* __restrict__ E1, const float* __restrict__ E2,
                       const float* __restrict__ E3, const float* __restrict__ E4,
                       const float* __restrict__ E5, float* __restrict__ out,
                       float w0, float w1, float we0, float we1, float we2,
                       float om0, float om1, float om2, float om3, float om4) {
    __shared__ float s_w[3][3][TROWS][TPITCH];
    __shared__ int s_mask;

    int tx = threadIdx.x, ty = threadIdx.y;
    int qx = blockIdx.x * TQX + tx;
    int qy = blockIdx.y * TQY + ty;
    int tid = ty * TQX + tx;

    float d2q[2][2] = {{3.4e38f, 3.4e38f}, {3.4e38f, 3.4e38f}};
    float x0 = (float)(2 * qx), y0 = (float)(2 * qy);
#pragma unroll
    for (int k = 0; k < 4; k++) {
        float dx = x0 - fixs[2 * k];
        float dy = y0 - fixs[2 * k + 1];
        float d00 = dx * dx + dy * dy;
        float tX = 2.f * dx + 1.f;
        float tY = 2.f * dy + 1.f;
        float d01 = d00 + tX;
        d2q[0][0] = fminf(d2q[0][0], d00);
        d2q[0][1] = fminf(d2q[0][1], d01);
        d2q[1][0] = fminf(d2q[1][0], d00 + tY);
        d2q[1][1] = fminf(d2q[1][1], d01 + tY);
    }

    int lv[2][2];
    float Rv[2][2];
#pragma unroll
    for (int py = 0; py < 2; py++)
#pragma unroll
        for (int px = 0; px < 2; px++) {
            float theta = sqrtf(d2q[py][px]) * (1.0f / 7.5f);
            float R = 2.5f / (theta + 2.5f);
            Rv[py][px] = R;
            lv[py][px] = (R <= om0) + (R <= om1) + (R <= om2) +
                         (R <= om3) + (R <= om4);
        }

    if (tid == 0) s_mask = 0;
    __syncthreads();
    int myMask = (1 << lv[0][0]) | (1 << lv[0][1]) | (1 << lv[1][0]) | (1 << lv[1][1]);
    atomicOr(&s_mask, myMask);
    __syncthreads();
    int mask = s_mask;
    int lmin = __ffs(mask) - 1;
    int lmax = 31 - __clz(mask);
    bool block_border = (blockIdx.x == 0) || (blockIdx.x == gridDim.x - 1) ||
                        (blockIdx.y == 0) || (blockIdx.y == gridDim.y - 1);

    int pix0 = (2 * qy) * WW + 2 * qx;

    if (!block_border && (lmax - lmin) <= 1) {
        if (mask == 1) {
#pragma unroll
            for (int c = 0; c < 3; c++) {
                *(float2*)(out + pix0 + c * HWFULL) =
                    *(const float2*)(img + pix0 + c * HWFULL);
                *(float2*)(out + pix0 + WW + c * HWFULL) =
                    *(const float2*)(img + pix0 + WW + c * HWFULL);
            }
            return;
        }
        int base = max(lmin, 1);
        bool hasP = (base >= 2);
        bool hasN = (lmax > base);
        const float* Ebase = level_ptr(base, E1, E2, E3, E4, E5);
        const float* Eprv = hasP ? level_ptr(base - 1, E1, E2, E3, E4, E5) : Ebase;
        const float* Enxt = hasN ? level_ptr(base + 1, E1, E2, E3, E4, E5) : Ebase;

        int ox0 = blockIdx.x * TQX - 1;
        int oy0 = blockIdx.y * TQY - 1;
        const int NFILL = 3 * TROWS * TPITCH;
        for (int i = tid; i < NFILL; i += 256) {
            int c = i / (TROWS * TPITCH);
            int rem = i - c * (TROWS * TPITCH);
            int r = rem / TPITCH, col = rem - r * TPITCH;
            size_t g = (size_t)c * NE * NE + (size_t)(oy0 + r) * NE + (ox0 + col);
            s_w[1][c][r][col] = Ebase[g];
            if (hasP) s_w[0][c][r][col] = Eprv[g];
            if (hasN) s_w[2][c][r][col] = Enxt[g];
        }
        __syncthreads();

        int lq = lv[0][0];
        bool uniq = (lv[0][1] == lq) && (lv[1][0] == lq) && (lv[1][1] == lq);

        if (uniq && lq == 0) {
#pragma unroll
            for (int c = 0; c < 3; c++) {
                *(float2*)(out + pix0 + c * HWFULL) =
                    *(const float2*)(img + pix0 + c * HWFULL);
                *(float2*)(out + pix0 + WW + c * HWFULL) =
                    *(const float2*)(img + pix0 + WW + c * HWFULL);
            }
            return;
        }

        if (uniq) {
            int cs = 1 + (lq - base);
            float B[2][2];
#pragma unroll
            for (int py = 0; py < 2; py++)
#pragma unroll
                for (int px = 0; px < 2; px++)
                    B[py][px] = blend_B(lq, Rv[py][px]);

#pragma unroll
            for (int c = 0; c < 3; c++) {
                const float (*wc)[TPITCH] = s_w[cs][c];
                float he[3], ho[3];
#pragma unroll
                for (int j = 0; j < 3; j++) {
                    float a = wc[ty + j][tx], b = wc[ty + j][tx + 1],
                          d = wc[ty + j][tx + 2];
                    he[j] = we0 * a + we1 * b + we2 * d;
                    ho[j] = we2 * a + we1 * b + we0 * d;
                }
                float vc[2][2];
                vc[0][0] = we0 * he[0] + we1 * he[1] + we2 * he[2];
                vc[0][1] = we0 * ho[0] + we1 * ho[1] + we2 * ho[2];
                vc[1][0] = we2 * he[0] + we1 * he[1] + we0 * he[2];
                vc[1][1] = we2 * ho[0] + we1 * ho[1] + we0 * ho[2];

                float vp[2][2];
                if (lq == 1) {
                    float2 i0 = *(const float2*)(img + pix0 + c * HWFULL);
                    float2 i1 = *(const float2*)(img + pix0 + WW + c * HWFULL);
                    vp[0][0] = i0.x; vp[0][1] = i0.y; vp[1][0] = i1.x; vp[1][1] = i1.y;
                } else {
                    const float (*wp)[TPITCH] = s_w[cs - 1][c];
                    float pe[3], po[3];
#pragma unroll
                    for (int j = 0; j < 3; j++) {
                        float a = wp[ty + j][tx], b = wp[ty + j][tx + 1],
                              d = wp[ty + j][tx + 2];
                        pe[j] = we0 * a + we1 * b + we2 * d;
                        po[j] = we2 * a + we1 * b + we0 * d;
                    }
                    vp[0][0] = we0 * pe[0] + we1 * pe[1] + we2 * pe[2];
                    vp[0][1] = we0 * po[0] + we1 * po[1] + we2 * po[2];
                    vp[1][0] = we2 * pe[0] + we1 * pe[1] + we0 * pe[2];
                    vp[1][1] = we2 * po[0] + we1 * po[1] + we0 * po[2];
                }
                float2 o0, o1;
                o0.x = B[0][0] * vp[0][0] + (1.f - B[0][0]) * vc[0][0];
                o0.y = B[0][1] * vp[0][1] + (1.f - B[0][1]) * vc[0][1];
                o1.x = B[1][0] * vp[1][0] + (1.f - B[1][0]) * vc[1][0];
                o1.y = B[1][1] * vp[1][1] + (1.f - B[1][1]) * vc[1][1];
                *(float2*)(out + pix0 + c * HWFULL) = o0;
                *(float2*)(out + pix0 + WW + c * HWFULL) = o1;
            }
            return;
        }

        float px_out[2][2][3];
#pragma unroll
        for (int py = 0; py < 2; py++)
#pragma unroll
            for (int px = 0; px < 2; px++) {
                int l = lv[py][px];
                int pp = pix0 + py * WW + px;
                if (l == 0) {
#pragma unroll
                    for (int c = 0; c < 3; c++)
                        px_out[py][px][c] = img[pp + c * HWFULL];
                } else {
                    int cs = 1 + (l - base);
                    float B = blend_B(l, Rv[py][px]);
#pragma unroll
                    for (int c = 0; c < 3; c++) {
                        float vc = evalw(s_w[cs][c], ty, tx, px, py, we0, we1, we2);
                        float vp = (l == 1) ? img[pp + c * HWFULL]
                                 : evalw(s_w[cs - 1][c], ty, tx, px, py, we0, we1, we2);
                        px_out[py][px][c] = B * vp + (1.f - B) * vc;
                    }
                }
            }
#pragma unroll
        for (int c = 0; c < 3; c++) {
            float2 o0, o1;
            o0.x = px_out[0][0][c]; o0.y = px_out[0][1][c];
            o1.x = px_out[1][0][c]; o1.y = px_out[1][1][c];
            *(float2*)(out + pix0 + c * HWFULL) = o0;
            *(float2*)(out + pix0 + WW + c * HWFULL) = o1;
        }
        return;
    }

    // fallback: border blocks / >2-level blocks (rare)
    int l0 = lv[0][0];
    bool uni = (lv[0][1] == l0) && (lv[1][0] == l0) && (lv[1][1] == l0);
    bool qborder = (qx == 0) | (qx >= NE - 1) | (qy == 0) | (qy >= NE - 1);

    if (uni && l0 == 0) {
#pragma unroll
        for (int c = 0; c < 3; c++) {
            *(float2*)(out + pix0 + c * HWFULL) =
                *(const float2*)(img + pix0 + c * HWFULL);
            *(float2*)(out + pix0 + WW + c * HWFULL) =
                *(const float2*)(img + pix0 + WW + c * HWFULL);
        }
        return;
    }
    if (!uni || qborder) {
#pragma unroll
        for (int py = 0; py < 2; py++)
#pragma unroll
            for (int px = 0; px < 2; px++)
                pixel_slow(2 * qx + px, 2 * qy + py, lv[py][px], Rv[py][px],
                           img, E1, E2, E3, E4, E5, out, w0, w1);
        return;
    }
    float B[2][2];
#pragma unroll
    for (int py = 0; py < 2; py++)
#pragma unroll
        for (int px = 0; px < 2; px++)
            B[py][px] = blend_B(l0, Rv[py][px]);
    const float* cur = level_ptr(l0, E1, E2, E3, E4, E5);
    const float* prv = level_ptr(l0 - 1, E1, E2, E3, E4, E5);
    quad_global(qx, qy, l0, B, img, cur, prv, out, we0, we1, we2);
}

// ---------------- host launch (graph fork-join parallelism) ----------------
extern "C" void kernel_launch(void* const* d_in, const int* in_sizes, int n_in,
                              void* d_out, int out_size) {
    const float* img = (const float*)d_in[0];
    const float* fixs = (const float*)d_in[1];
    float* out = (float*)d_out;

    float *pyr1, *pyr2, *pyr3, *pyr4, *pyr5, *E2, *E3, *E4, *E5;
    cudaGetSymbolAddress((void**)&pyr1, g_pyr1);
    cudaGetSymbolAddress((void**)&pyr2, g_pyr2);
    cudaGetSymbolAddress((void**)&pyr3, g_pyr3);
    cudaGetSymbolAddress((void**)&pyr4, g_pyr4);
    cudaGetSymbolAddress((void**)&pyr5, g_pyr5);
    cudaGetSymbolAddress((void**)&E2, g_E2);
    cudaGetSymbolAddress((void**)&E3, g_E3);
    cudaGetSymbolAddress((void**)&E4, g_E4);
    cudaGetSymbolAddress((void**)&E5, g_E5);

    // Gaussian taps (w2 ~ 7.5e-15 dropped from taps; kept in normalization)
    double s2c = 2.0 * 0.248 * 0.248;
    double g1 = exp(-1.0 / s2c);
    double g2 = exp(-4.0 / s2c);
    double nrm = 1.0 + 2.0 * g1 + 2.0 * g2;
    float w0 = (float)(1.0 / nrm);
    float w1 = (float)(g1 / nrm);
    float De = (float)(0.5 * g1 / nrm);
    float Dm = (float)(0.5 * (1.0 + g1) / nrm);
    float we0 = 0.25f * w0 + 0.75f * w1;
    float we1 = 0.75f * w0 + w1;
    float we2 = 0.25f * w1;

    double ob = sqrt(log(2.0) / 3.0) * 0.248;
    float om0 = (float)(ob * 4.0);
    float om1 = (float)(ob * 2.0);
    float om2 = (float)(ob);
    float om3 = (float)(ob * 0.5);
    float om4 = (float)(ob * 0.25);

    // side stream + events, created once on the first (uncaptured) call
    static cudaStream_t sSide = 0;
    static cudaEvent_t evStart = 0, evW = 0, evB512 = 0, evE2 = 0;
    if (!sSide) {
        cudaStreamCreateWithFlags(&sSide, cudaStreamNonBlocking);
        cudaEventCreateWithFlags(&evStart, cudaEventDisableTiming);
        cudaEventCreateWithFlags(&evW, cudaEventDisableTiming);
        cudaEventCreateWithFlags(&evB512, cudaEventDisableTiming);
        cudaEventCreateWithFlags(&evE2, cudaEventDisableTiming);
    }

    dim3 blk(32, 8);

    // fork: side stream joins the capture via evStart
    cudaEventRecord(evStart, 0);
    cudaStreamWaitEvent(sSide, evStart, 0);

    // side: weight tables (data-independent)
    weight_table_kernel<<<dim3(16, 4), 64, 0, sSide>>>(w0, w1);
    cudaEventRecord(evW, sSide);

    // main: big pyramid levels
    blur_down2_kernel<<<dim3(16, 128, 3), blk>>>(img, pyr1, 1024, De, Dm);
    blur_down2_kernel<<<dim3(8, 64, 3), blk>>>(pyr1, pyr2, 512, De, Dm);
    cudaEventRecord(evB512, 0);

    // side: expand E2 (needs pyr2 + tables) concurrent with down_small/expandB
    cudaStreamWaitEvent(sSide, evB512, 0);
    expand_direct_kernel<<<dim3(16, 16, 3), 256, 0, sSide>>>(
        pyr2, pyr3, pyr4, pyr5, E2, E3, E4, E5, 0, 1);
    cudaEventRecord(evE2, sSide);

    // main: small pyramid chain, then deep expansions (need tables)
    down_small_kernel<<<dim3(16, 16, 3), 256>>>(pyr2, pyr3, pyr4, pyr5, De, Dm);
    cudaStreamWaitEvent(0, evW, 0);
    expand_direct_kernel<<<dim3(16, 16, 9), 256>>>(
        pyr2, pyr3, pyr4, pyr5, E2, E3, E4, E5, 1, 3);

    // join: blend needs E2 from the side branch
    cudaStreamWaitEvent(0, evE2, 0);
    blend_quad_kernel<<<dim3(NE / 32, NE / 8), blk>>>(img, fixs, pyr1, E2, E3, E4, E5,
                                                      out, w0, w1, we0, we1, we2,
                                                      om0, om1, om2, om3, om4);
}